// round 1
// baseline (speedup 1.0000x reference)
#include <cuda_runtime.h>
#include <math.h>

#define BSZ 4
#define CC  4
#define NN  2048
#define DD  16
#define KK  32
#define MM  64
#define NPB 16

// scratch (allocation-free rule: device globals)
__device__ int   g_nbr  [BSZ*CC*NN*KK];
__device__ float g_theta[BSZ*CC*NN*KK];
__device__ float g_gate [BSZ*CC*NN*KK];

// ---------------------------------------------------------------------------
// Kernel 1: per-(b,c) KNN (top-33 incl. self), direction cosines, gate.
// Block: 256 threads = 128 rows x 2 j-splits. Grid: (N/128, BS*C).
// ---------------------------------------------------------------------------
__global__ __launch_bounds__(256) void knn_kernel(
    const float* __restrict__ pos, const float* __restrict__ node_mask,
    const float* __restrict__ rw1, const float* __restrict__ rw2)
{
    extern __shared__ char smem_raw[];
    float4* spos = (float4*)smem_raw;                        // 2048*16 = 32768B
    float*  smd  = (float*)(smem_raw + NN*16);               // 128*33*4
    int*    smi  = (int*)  (smem_raw + NN*16 + 128*33*4);    // 128*33*4

    const int slice = blockIdx.y;            // b*C + c
    const int b     = slice / CC;
    const float* p  = pos + (size_t)slice * NN * 3;
    const int tid   = threadIdx.x;
    const int row_local = tid & 127;
    const int split     = tid >> 7;

    for (int j = tid; j < NN; j += 256) {
        float x = p[3*j], y = p[3*j+1], z = p[3*j+2];
        float q = fmaf(z, z, fmaf(y, y, x*x));
        spos[j] = make_float4(x, y, z, q);
    }

    // gate MLP is piecewise-linear in dist: f(d) = d * (d>=0 ? Spos : Sneg)
    float Spos = 0.f, Sneg = 0.f;
    #pragma unroll
    for (int m = 0; m < MM; m++) {
        float a = __ldg(rw1 + m), w = __ldg(rw2 + m);
        Spos = fmaf(fmaxf(a, 0.f), w, Spos);
        Sneg = fmaf(fminf(a, 0.f), w, Sneg);
    }
    __syncthreads();

    const int i = blockIdx.x * 128 + row_local;
    const float4 pi = spos[i];

    // sorted top-33 smallest (d, j) lexicographic (matches top_k tie rule)
    float bd[33]; int bix[33];
    #pragma unroll
    for (int t = 0; t < 33; t++) { bd[t] = INFINITY; bix[t] = 0x7fffffff; }
    float worst = INFINITY; int worsti = 0x7fffffff;

    const int j0 = split * (NN / 2);
    #pragma unroll 4
    for (int jj = 0; jj < NN / 2; jj++) {
        const int j = j0 + jj;
        float4 pj = spos[j];
        float dot = fmaf(pi.z, pj.z, fmaf(pi.y, pj.y, pi.x * pj.x));
        float d   = fmaf(-2.f, dot, pj.w) + pi.w;   // -2*inner + q_j + q_i
        if (d < worst || (d == worst && j < worsti)) {
            int q = 32;
            while (q > 0 && (d < bd[q-1] || (d == bd[q-1] && j < bix[q-1]))) {
                bd[q] = bd[q-1]; bix[q] = bix[q-1]; q--;
            }
            bd[q] = d; bix[q] = j;
            worst = bd[32]; worsti = bix[32];
        }
    }

    if (split == 1) {
        #pragma unroll
        for (int t = 0; t < 33; t++) {
            smd[row_local*33 + t] = bd[t];
            smi[row_local*33 + t] = bix[t];
        }
    }
    __syncthreads();
    if (split == 1) return;   // no further barriers below

    // merge the two sorted 33-lists
    float od[33]; int oi[33];
    {
        const float* sdB = smd + row_local*33;
        const int*   siB = smi + row_local*33;
        int a = 0, bq = 0;
        #pragma unroll
        for (int t = 0; t < 33; t++) {
            float da = bd[a];  int ia = bix[a];
            float db = sdB[bq]; int ib = siB[bq];
            bool ta = (da < db) || (da == db && ia < ib);
            if (ta) { od[t] = da; oi[t] = ia; a++; }
            else    { od[t] = db; oi[t] = ib; bq++; }
        }
    }
    // od[0]/oi[0] is self (dist exactly 0) -> neighbors are entries 1..32

    const float mk = node_mask[b*NN + i];

    const int nb0 = oi[1];
    float4 p0 = spos[nb0];
    float d0x = p0.x - pi.x, d0y = p0.y - pi.y, d0z = p0.z - pi.z;
    float n0  = sqrtf(d0x*d0x + d0y*d0y + d0z*d0z);
    float inv0 = 1.f / fmaxf(n0, 1e-12f);
    d0x *= inv0; d0y *= inv0; d0z *= inv0;

    const size_t base = ((size_t)slice * NN + i) * KK;
    #pragma unroll 4
    for (int k = 0; k < KK; k++) {
        const int nb = oi[k+1];
        const float dist = od[k+1];
        float cosv = 1.f;
        if (k > 0) {
            float4 pn = spos[nb];
            float dx = pn.x - pi.x, dy = pn.y - pi.y, dz = pn.z - pi.z;
            float nrm = sqrtf(dx*dx + dy*dy + dz*dz);
            float inv = 1.f / fmaxf(nrm, 1e-12f);
            cosv = (dx*d0x + dy*d0y + dz*d0z) * inv;
        }
        const float S  = (dist >= 0.f) ? Spos : Sneg;
        const float gb = fmaxf(dist * S, 0.f) * mk;     // relu(a @ w2) * mask
        const float gate = 1.f / (1.f + expf(-gb));
        g_nbr  [base + k] = nb;
        g_theta[base + k] = cosv * mk;
        g_gate [base + k] = gate;
    }
}

// ---------------------------------------------------------------------------
// Kernel 2: fused gather + gated feature GEMV + angle GEMV + leaky_relu.
// Block: 128 threads, handles NPB=16 nodes of one batch. Grid: BS*(N/NPB).
// ---------------------------------------------------------------------------
__global__ __launch_bounds__(128) void fuse_kernel(
    const float* __restrict__ node_fea, const float* __restrict__ node_mask,
    const float* __restrict__ aw, const float* __restrict__ sw,
    float* __restrict__ out)
{
    extern __shared__ char smem_raw[];
    float* sawT = (float*)smem_raw;                 // [f][m] padded: 128*65
    float* ssw  = (float*)(smem_raw + 128*65*4);    // [f][m]: 128*64
    __shared__ float su[128];
    __shared__ float stheta[128];
    __shared__ float sgate[128];
    __shared__ int   snbr[128];
    __shared__ float sout[MM][NPB];

    const int tid = threadIdx.x;

    // stage weights: aw is (M=64, 128) -> transpose; sw is (128, M=64) -> copy
    for (int idx = tid; idx < MM*128; idx += 128) {
        int m = idx >> 7, f = idx & 127;
        sawT[f*65 + m] = aw[idx];
    }
    for (int idx = tid; idx < 128*MM; idx += 128)
        ssw[idx] = sw[idx];

    const int b  = blockIdx.x >> 7;            // N/NPB = 128 blocks per batch
    const int n0 = (blockIdx.x & 127) * NPB;
    __syncthreads();

    const int c  = tid >> 5;
    const int kk = tid & 31;

    for (int nn = 0; nn < NPB; nn++) {
        const int n = n0 + nn;
        {
            const size_t eb = (((size_t)(b*CC + c) * NN) + n) * KK + kk;
            snbr[tid]   = g_nbr[eb];
            stheta[tid] = g_theta[eb];
            sgate[tid]  = g_gate[eb];
        }
        __syncthreads();
        {
            const float* nf = node_fea + ((size_t)(b*CC + c) * NN) * DD;
            float u;
            if (kk < DD) {                      // self term: (sum_k gate)*fea
                float G = 0.f;
                #pragma unroll
                for (int k = 0; k < KK; k++) G += sgate[c*32 + k];
                u = G * __ldg(nf + (size_t)n*DD + kk);
            } else {                            // neighbor term: gather
                const int t = kk - DD;
                float v = 0.f;
                #pragma unroll 8
                for (int k = 0; k < KK; k++)
                    v = fmaf(sgate[c*32 + k],
                             __ldg(nf + (size_t)snbr[c*32 + k]*DD + t), v);
                u = v;
            }
            su[tid] = u;
        }
        __syncthreads();
        if (tid < MM) {
            const int m = tid;
            float fs = 0.f;                      // angle_weight @ theta (f=k*C+c)
            #pragma unroll 8
            for (int k = 0; k < KK; k++)
                #pragma unroll
                for (int c2 = 0; c2 < CC; c2++)
                    fs = fmaf(sawT[(k*CC + c2)*65 + m], stheta[c2*32 + k], fs);
            float fe = 0.f;                      // fea_gated @ scalar_weight
            #pragma unroll 16
            for (int f = 0; f < 128; f++)
                fe = fmaf(ssw[f*64 + m], su[f], fe);
            const float mk = node_mask[b*NN + n];
            const float val = fmaf(fe, mk, fs);  // theta already masked
            const float r = (val >= 0.f) ? val : 0.01f * val;
            sout[m][nn] = r * mk;
        }
        __syncthreads();
    }

    // coalesced output: out layout (b, m, n)
    for (int idx = tid; idx < MM*NPB; idx += 128) {
        int m = idx / NPB, nn = idx % NPB;
        out[((size_t)b*MM + m)*NN + n0 + nn] = sout[m][nn];
    }
}

// ---------------------------------------------------------------------------
extern "C" void kernel_launch(void* const* d_in, const int* in_sizes, int n_in,
                              void* d_out, int out_size)
{
    const float* pos       = (const float*)d_in[0];
    const float* node_fea  = (const float*)d_in[1];
    const float* node_mask = (const float*)d_in[2];
    const float* aw        = (const float*)d_in[3];
    const float* sw        = (const float*)d_in[4];
    const float* rw1       = (const float*)d_in[5];
    const float* rw2       = (const float*)d_in[6];
    float* out = (float*)d_out;

    const int smem1 = NN*16 + 128*33*4*2;      // 66560B
    const int smem2 = 128*65*4 + 128*64*4;     // 66048B
    cudaFuncSetAttribute(knn_kernel,  cudaFuncAttributeMaxDynamicSharedMemorySize, smem1);
    cudaFuncSetAttribute(fuse_kernel, cudaFuncAttributeMaxDynamicSharedMemorySize, smem2);

    knn_kernel<<<dim3(NN/128, BSZ*CC), 256, smem1>>>(pos, node_mask, rw1, rw2);
    fuse_kernel<<<BSZ*(NN/NPB), 128, smem2>>>(node_fea, node_mask, aw, sw, out);
}

// round 2
// speedup vs baseline: 35.6727x; 35.6727x over previous
#include <cuda_runtime.h>
#include <math.h>

#define BSZ 4
#define CC  4
#define NN  2048
#define DD  16
#define KK  32
#define MM  64

// scratch (allocation-free rule: device globals)
__device__ int   g_nbr  [BSZ*CC*NN*KK];
__device__ float g_theta[BSZ*CC*NN*KK];
__device__ float g_gate [BSZ*CC*NN*KK];

__device__ __forceinline__ unsigned long long warpmin64(unsigned long long p) {
    #pragma unroll
    for (int o = 16; o; o >>= 1) {
        unsigned long long q = __shfl_xor_sync(0xffffffffu, p, o);
        if (q < p) p = q;
    }
    return p;
}

// ---------------------------------------------------------------------------
// Kernel 1 v2: warp-per-row KNN top-33 via shared-memory distance row +
// packed-u64 segmented min extraction. Block = 512 thr = 16 rows.
// Grid: (N/16, BS*C).
// ---------------------------------------------------------------------------
#define ROWS 16
#define SDPITCH 2112   // 2048 + 64 padding: phys(j) = j + (j>>5)

__global__ __launch_bounds__(512) void knn_kernel(
    const float* __restrict__ pos, const float* __restrict__ node_mask,
    const float* __restrict__ rw1, const float* __restrict__ rw2)
{
    extern __shared__ char smem_raw[];
    float4* spos = (float4*)smem_raw;                                  // 32768B
    float*  sdist = (float*)(smem_raw + NN*16);                        // 16*2112*4
    unsigned long long* sres =
        (unsigned long long*)(smem_raw + NN*16 + ROWS*SDPITCH*4);      // 16*33*8

    __shared__ float sSpos;

    const int tid  = threadIdx.x;
    const int warp = tid >> 5;
    const int lane = tid & 31;
    const int slice = blockIdx.y;            // b*C + c
    const int b     = slice / CC;
    const float* p  = pos + (size_t)slice * NN * 3;

    for (int j = tid; j < NN; j += 512) {
        float x = p[3*j], y = p[3*j+1], z = p[3*j+2];
        float q = fmaf(z, z, fmaf(y, y, x*x));
        spos[j] = make_float4(x, y, z, q);
    }

    // gate MLP collapses: relu(sum_m relu(d*w1)*w2) = relu(d*Spos) for d>=0
    if (tid < 32) {
        float a1 = rw1[tid],    w1v = rw2[tid];
        float a2 = rw1[tid+32], w2v = rw2[tid+32];
        float sp = fmaf(fmaxf(a1, 0.f), w1v, fmaxf(a2, 0.f) * w2v);
        #pragma unroll
        for (int o = 16; o; o >>= 1) sp += __shfl_xor_sync(0xffffffffu, sp, o);
        if (tid == 0) sSpos = sp;
    }
    __syncthreads();

    const int i = blockIdx.x * ROWS + warp;
    const float4 pi = spos[i];
    float* sd = sdist + warp * SDPITCH;
    unsigned long long* res = sres + warp * 33;

    // distance phase: lane owns segment {j : j%32 == lane}
    unsigned long long seg = 0xFFFFFFFFFFFFFFFFull;
    #pragma unroll 4
    for (int t = 0; t < 64; t++) {
        const int j = t*32 + lane;
        float4 pj = spos[j];
        float dot = fmaf(pi.z, pj.z, fmaf(pi.y, pj.y, pi.x * pj.x));
        float d   = fmaf(-2.f, dot, pj.w) + pi.w;
        d = fmaxf(d, 0.f);                   // self is exactly 0; others >> 0
        sd[t*33 + lane] = d;                 // phys(j) = 33t+lane, conflict-free
        unsigned long long pk =
            ((unsigned long long)__float_as_uint(d) << 32) | (unsigned)j;
        if (pk < seg) seg = pk;
    }
    __syncwarp();

    // extract 33 smallest (self + 32 neighbors), ascending (d, j)
    #pragma unroll 1
    for (int e = 0; e < 33; e++) {
        unsigned long long pmin = warpmin64(seg);
        if (lane == 0) res[e] = pmin;
        const int jw = (int)(unsigned)pmin;          // low word = j
        const int w  = jw & 31;                      // owner segment
        if (lane == 0) sd[jw + (jw >> 5)] = INFINITY;
        __syncwarp();
        // warp-parallel rescan of segment w (padding -> conflict-free)
        float d1 = sd[33*lane + w];
        float d2 = sd[33*(lane+32) + w];
        unsigned long long q1 =
            ((unsigned long long)__float_as_uint(d1) << 32) | (unsigned)(lane*32 + w);
        unsigned long long q2 =
            ((unsigned long long)__float_as_uint(d2) << 32) | (unsigned)((lane+32)*32 + w);
        if (q2 < q1) q1 = q2;
        q1 = warpmin64(q1);
        if (lane == w) seg = q1;
    }
    __syncwarp();

    // outputs: lane k handles neighbor k = res[k+1]
    const float mk = node_mask[b*NN + i];
    const float Spos = sSpos;

    unsigned long long p1 = res[1];
    const int nb0 = (int)(unsigned)p1;
    float4 pn0 = spos[nb0];
    float d0x = pn0.x - pi.x, d0y = pn0.y - pi.y, d0z = pn0.z - pi.z;
    float n0  = sqrtf(d0x*d0x + d0y*d0y + d0z*d0z);
    float inv0 = 1.f / fmaxf(n0, 1e-12f);
    d0x *= inv0; d0y *= inv0; d0z *= inv0;

    unsigned long long pk = res[lane + 1];
    const int   nb   = (int)(unsigned)pk;
    const float dist = __uint_as_float((unsigned)(pk >> 32));

    float cosv = 1.f;
    if (lane > 0) {
        float4 pn = spos[nb];
        float dx = pn.x - pi.x, dy = pn.y - pi.y, dz = pn.z - pi.z;
        float nrm = sqrtf(dx*dx + dy*dy + dz*dz);
        float inv = 1.f / fmaxf(nrm, 1e-12f);
        cosv = (dx*d0x + dy*d0y + dz*d0z) * inv;
    }
    const float gb   = fmaxf(dist * Spos, 0.f) * mk;
    const float gate = 1.f / (1.f + __expf(-gb));

    const size_t base = ((size_t)slice * NN + i) * KK;
    g_nbr  [base + lane] = nb;
    g_theta[base + lane] = cosv * mk;
    g_gate [base + lane] = gate;
}

// ---------------------------------------------------------------------------
// Kernel 2 v2: gather + gated feature GEMV + angle GEMV, register-tiled.
// Block = 256 threads, 16 nodes. Grid = BS*(N/16) = 512.
// ---------------------------------------------------------------------------
#define NB 16

// shared offsets (bytes)
#define OFF_SSW    0
#define OFF_SAWT   32768
#define OFF_SU     65536
#define OFF_STHETA (OFF_SU + 8192)
#define OFF_SGATE  (OFF_STHETA + 8192)
#define OFF_SNBR   (OFF_SGATE + 8192)
#define OFF_SG     (OFF_SNBR + 8192)
#define OFF_SOUT   (OFF_SG + 256)
#define OFF_ARAW   OFF_SU                    // overlay: used before su etc.
#define SMEM2_TOTAL (OFF_SOUT + 64*17*4)     // 102912

__global__ __launch_bounds__(256) void fuse_kernel(
    const float* __restrict__ node_fea, const float* __restrict__ node_mask,
    const float* __restrict__ aw, const float* __restrict__ sw,
    float* __restrict__ out)
{
    extern __shared__ char smem_raw[];
    float* ssw    = (float*)(smem_raw + OFF_SSW);     // [f][64]
    float* sawT   = (float*)(smem_raw + OFF_SAWT);    // [f][64]
    float* su     = (float*)(smem_raw + OFF_SU);      // [16][128]
    float* stheta = (float*)(smem_raw + OFF_STHETA);  // [16][128]
    float* sgate  = (float*)(smem_raw + OFF_SGATE);   // [4][16][32]
    int*   snbr   = (int*)  (smem_raw + OFF_SNBR);
    float* sG     = (float*)(smem_raw + OFF_SG);      // [16][4]
    float* sout   = (float*)(smem_raw + OFF_SOUT);    // [64][17]
    float* araw   = (float*)(smem_raw + OFF_ARAW);    // [64][129] overlay

    const int tid = threadIdx.x;
    const int b   = blockIdx.x >> 7;
    const int n0  = (blockIdx.x & 127) * NB;

    // stage 1: raw weights
    for (int idx = tid; idx < MM*128; idx += 256) {
        int m = idx >> 7, f = idx & 127;
        araw[m*129 + f] = aw[idx];          // coalesced read, stride-1 write
        ssw[idx] = sw[idx];                 // sw already [f][64]
    }
    __syncthreads();
    // stage 2: transpose aw -> sawT [f][64]  (129-pad => conflict-free reads)
    for (int idx = tid; idx < MM*128; idx += 256) {
        int f = idx >> 6, m = idx & 63;
        sawT[f*64 + m] = araw[m*129 + f];
    }
    __syncthreads();
    // stage 3: edge staging (overwrites araw region)
    for (int idx = tid; idx < 2048; idx += 256) {
        int c = idx >> 9, r = idx & 511;            // r = nn*32 + k
        size_t src = (size_t)(b*CC + c)*NN*KK + (size_t)n0*KK + r;
        float gv = g_gate[src];
        sgate[c*512 + r] = gv;
        snbr [c*512 + r] = g_nbr[src];
        int nn = r >> 5, k = r & 31;
        stheta[nn*128 + k*4 + c] = g_theta[src];
    }
    __syncthreads();
    if (tid < 64) {                                  // gate sums per (nn, c)
        int nn = tid >> 2, c = tid & 3;
        float G = 0.f;
        #pragma unroll
        for (int k = 0; k < KK; k++) G += sgate[c*512 + nn*32 + k];
        sG[tid] = G;
    }
    __syncthreads();

    // phase A: build su[nn][f]; thread = (nn, c, t4)
    {
        const int nn = tid >> 4, c = (tid >> 2) & 3, t4 = tid & 3;
        const float* nf = node_fea + (size_t)(b*CC + c) * NN * DD;
        const int eb = c*512 + nn*32;
        float4 acc = make_float4(0.f, 0.f, 0.f, 0.f);
        #pragma unroll 8
        for (int k = 0; k < KK; k++) {
            float g = sgate[eb + k];
            int   nb = snbr[eb + k];
            float4 v = *(const float4*)(nf + (size_t)nb*DD + t4*4);
            acc.x = fmaf(g, v.x, acc.x); acc.y = fmaf(g, v.y, acc.y);
            acc.z = fmaf(g, v.z, acc.z); acc.w = fmaf(g, v.w, acc.w);
        }
        *(float4*)&su[nn*128 + c*32 + 16 + t4*4] = acc;
        float4 fv = *(const float4*)(nf + (size_t)(n0+nn)*DD + t4*4);
        float Gs = sG[nn*4 + c];
        float4 sv = make_float4(Gs*fv.x, Gs*fv.y, Gs*fv.z, Gs*fv.w);
        *(float4*)&su[nn*128 + c*32 + t4*4] = sv;
    }
    __syncthreads();

    // phase B: outputs; thread = (n, m0..m0+3), 8 independent fma chains
    {
        const int n = tid >> 4, m0 = (tid & 15) * 4;
        float e0=0,e1=0,e2=0,e3=0, s0=0,s1=0,s2=0,s3=0;
        const float* sun = su + n*128;
        const float* stn = stheta + n*128;
        #pragma unroll 8
        for (int f = 0; f < 128; f++) {
            float uf = sun[f], th = stn[f];
            float4 w1 = *(const float4*)&ssw [f*64 + m0];
            float4 w2 = *(const float4*)&sawT[f*64 + m0];
            e0 = fmaf(uf, w1.x, e0); e1 = fmaf(uf, w1.y, e1);
            e2 = fmaf(uf, w1.z, e2); e3 = fmaf(uf, w1.w, e3);
            s0 = fmaf(th, w2.x, s0); s1 = fmaf(th, w2.y, s1);
            s2 = fmaf(th, w2.z, s2); s3 = fmaf(th, w2.w, s3);
        }
        const float mk = node_mask[b*NN + n0 + n];
        float v0 = fmaf(e0, mk, s0), v1 = fmaf(e1, mk, s1);
        float v2 = fmaf(e2, mk, s2), v3 = fmaf(e3, mk, s3);
        v0 = (v0 >= 0.f) ? v0 : 0.01f*v0;  v1 = (v1 >= 0.f) ? v1 : 0.01f*v1;
        v2 = (v2 >= 0.f) ? v2 : 0.01f*v2;  v3 = (v3 >= 0.f) ? v3 : 0.01f*v3;
        sout[(m0+0)*17 + n] = v0*mk;  sout[(m0+1)*17 + n] = v1*mk;
        sout[(m0+2)*17 + n] = v2*mk;  sout[(m0+3)*17 + n] = v3*mk;
    }
    __syncthreads();

    for (int idx = tid; idx < MM*NB; idx += 256) {
        int m = idx >> 4, n = idx & 15;
        out[((size_t)b*MM + m)*NN + n0 + n] = sout[m*17 + n];
    }
}

// ---------------------------------------------------------------------------
extern "C" void kernel_launch(void* const* d_in, const int* in_sizes, int n_in,
                              void* d_out, int out_size)
{
    const float* pos       = (const float*)d_in[0];
    const float* node_fea  = (const float*)d_in[1];
    const float* node_mask = (const float*)d_in[2];
    const float* aw        = (const float*)d_in[3];
    const float* sw        = (const float*)d_in[4];
    const float* rw1       = (const float*)d_in[5];
    const float* rw2       = (const float*)d_in[6];
    float* out = (float*)d_out;

    const int smem1 = NN*16 + ROWS*SDPITCH*4 + ROWS*33*8;   // 172160
    cudaFuncSetAttribute(knn_kernel,  cudaFuncAttributeMaxDynamicSharedMemorySize, smem1);
    cudaFuncSetAttribute(fuse_kernel, cudaFuncAttributeMaxDynamicSharedMemorySize, SMEM2_TOTAL);

    knn_kernel<<<dim3(NN/ROWS, BSZ*CC), 512, smem1>>>(pos, node_mask, rw1, rw2);
    fuse_kernel<<<BSZ*(NN/NB), 256, SMEM2_TOTAL>>>(node_fea, node_mask, aw, sw, out);
}

// round 3
// speedup vs baseline: 52.9491x; 1.4843x over previous
#include <cuda_runtime.h>
#include <math.h>

#define BSZ 4
#define CC  4
#define NN  2048
#define DD  16
#define KK  32
#define MM  64
#define FULLM 0xffffffffu

// scratch (allocation-free rule: device globals)
__device__ int   g_nbr  [BSZ*CC*NN*KK];
__device__ float g_theta[BSZ*CC*NN*KK];
__device__ float g_gate [BSZ*CC*NN*KK];
__device__ float g_gsum [BSZ*CC*NN];

// ---------------------------------------------------------------------------
// Kernel 1 v3: warp-per-row KNN top-33. REDUX-based extraction, rescans
// recompute distances from a segment-major spos copy. 64KB smem -> 3 blk/SM.
// ---------------------------------------------------------------------------
#define ROWS1 16

__global__ __launch_bounds__(512, 3) void knn_kernel(
    const float* __restrict__ pos, const float* __restrict__ node_mask,
    const float* __restrict__ rw1, const float* __restrict__ rw2)
{
    extern __shared__ char sm1[];
    float4* spos  = (float4*)sm1;              // [j]          32KB
    float4* spos2 = (float4*)(sm1 + 32768);    // [w*64 + t]   32KB
    __shared__ float sSpos;

    const int tid  = threadIdx.x;
    const int warp = tid >> 5;
    const int lane = tid & 31;
    const int slice = blockIdx.y;              // b*C + c
    const int b     = slice >> 2;
    const float* p  = pos + (size_t)slice * NN * 3;

    for (int j = tid; j < NN; j += 512) {
        float x = p[3*j], y = p[3*j+1], z = p[3*j+2];
        float q = fmaf(z, z, fmaf(y, y, x*x));
        float4 f4 = make_float4(x, y, z, q);
        spos[j] = f4;
        spos2[(j & 31)*64 + (j >> 5)] = f4;
    }

    // gate MLP collapses: relu(sum_m relu(d*w1)*w2) = relu(d*Spos) for d>=0
    if (tid < 32) {
        float a1 = rw1[tid],    w1v = rw2[tid];
        float a2 = rw1[tid+32], w2v = rw2[tid+32];
        float sp = fmaf(fmaxf(a1, 0.f), w1v, fmaxf(a2, 0.f) * w2v);
        #pragma unroll
        for (int o = 16; o; o >>= 1) sp += __shfl_xor_sync(FULLM, sp, o);
        if (tid == 0) sSpos = sp;
    }
    __syncthreads();

    const int i = blockIdx.x * ROWS1 + warp;
    const float4 pi = spos[i];

    // distance phase: lane owns segment {j : j%32 == lane}; keep seg min
    unsigned segd = 0xffffffffu; int segj = 0;
    #pragma unroll 8
    for (int t = 0; t < 64; t++) {
        const int j = t*32 + lane;
        float4 pj = spos[j];
        float dot = fmaf(pi.z, pj.z, fmaf(pi.y, pj.y, pi.x * pj.x));
        float d   = fmaf(-2.f, dot, pj.w) + pi.w;
        d = fmaxf(d, 0.f);                  // self is exactly 0
        unsigned db = __float_as_uint(d);   // nonneg float: bits order = value order
        if (db < segd) { segd = db; segj = j; }   // strict < : earliest j on tie
    }

    // extract 33 smallest in ascending (d, j); lane e-1 keeps extraction e
    unsigned nbd = 0; int nbj = 0;
    #pragma unroll 1
    for (int e = 0; e < 33; e++) {
        unsigned dmin = __reduce_min_sync(FULLM, segd);
        unsigned cj   = (segd == dmin) ? (unsigned)segj : 0xffffffffu;
        unsigned jmin = __reduce_min_sync(FULLM, cj);
        if (lane == e - 1) { nbd = dmin; nbj = (int)jmin; }
        if (e == 32) break;
        const unsigned dL = dmin, jL = jmin;
        const int w = (int)(jmin & 31u);
        // rescan segment w: keep only keys strictly greater than (dL, jL)
        float4 a  = spos2[w*64 + lane];
        float4 bb = spos2[w*64 + 32 + lane];
        float dota = fmaf(pi.z, a.z,  fmaf(pi.y, a.y,  pi.x * a.x));
        float dotb = fmaf(pi.z, bb.z, fmaf(pi.y, bb.y, pi.x * bb.x));
        float da = fmaxf(fmaf(-2.f, dota, a.w)  + pi.w, 0.f);
        float db = fmaxf(fmaf(-2.f, dotb, bb.w) + pi.w, 0.f);
        unsigned u1 = __float_as_uint(da), u2 = __float_as_uint(db);
        unsigned j1 = (unsigned)(lane*32 + w), j2 = (unsigned)((lane+32)*32 + w);
        bool ok1 = (u1 > dL) || (u1 == dL && j1 > jL);
        bool ok2 = (u2 > dL) || (u2 == dL && j2 > jL);
        if (!ok1) u1 = 0xffffffffu;
        if (!ok2) u2 = 0xffffffffu;
        unsigned ub, jb;                      // j1 < j2 so tie -> pick 1
        if (u1 <= u2) { ub = u1; jb = j1; } else { ub = u2; jb = j2; }
        unsigned rd  = __reduce_min_sync(FULLM, ub);
        unsigned rcj = (ub == rd) ? jb : 0xffffffffu;
        unsigned rj  = __reduce_min_sync(FULLM, rcj);
        if (lane == w) { segd = rd; segj = (int)rj; }
    }

    // lane k holds neighbor k = (nbd, nbj)
    const float mk   = node_mask[b*NN + i];
    const float Spos = sSpos;
    const float dist = __uint_as_float(nbd);
    const int   nb   = nbj;

    const int nb0 = __shfl_sync(FULLM, nbj, 0);
    float4 pn0 = spos[nb0];
    float d0x = pn0.x - pi.x, d0y = pn0.y - pi.y, d0z = pn0.z - pi.z;
    float n0  = sqrtf(d0x*d0x + d0y*d0y + d0z*d0z);
    float inv0 = 1.f / fmaxf(n0, 1e-12f);
    d0x *= inv0; d0y *= inv0; d0z *= inv0;

    float cosv = 1.f;
    if (lane > 0) {
        float4 pn = spos[nb];
        float dx = pn.x - pi.x, dy = pn.y - pi.y, dz = pn.z - pi.z;
        float nrm = sqrtf(dx*dx + dy*dy + dz*dz);
        float inv = 1.f / fmaxf(nrm, 1e-12f);
        cosv = (dx*d0x + dy*d0y + dz*d0z) * inv;
    }
    const float gb   = fmaxf(dist * Spos, 0.f) * mk;
    const float gate = 1.f / (1.f + __expf(-gb));

    float G = gate;
    #pragma unroll
    for (int o = 16; o; o >>= 1) G += __shfl_xor_sync(FULLM, G, o);

    const size_t base = ((size_t)slice * NN + i) * KK;
    g_nbr  [base + lane] = nb;
    g_theta[base + lane] = cosv * mk;
    g_gate [base + lane] = gate;
    if (lane == 0) g_gsum[(size_t)slice*NN + i] = G;
}

// ---------------------------------------------------------------------------
// Kernel 2 v3: 64 nodes/block, fused dual-GEMV with 4m x 4n register tile.
// Grid = BS*(N/64) = 128, block = 256.
// ---------------------------------------------------------------------------
// smem float offsets
#define O_SSW   0                      // [f][64 m]   8192
#define O_SAWT  8192                   // [f][64 m]   8192
#define O_SU    16384                  // [f][64 n]   8192
#define O_STH   24576                  // [f pitch68] 8704
#define O_SGATE 33280                  // [c][k p66][n] 8448
#define O_SNBR  41728                  // [c][k p66][n] 8448
#define O_ARAW  16384                  // overlay [64][129] = 8256 (pre-staging)
#define SMEM2_FLOATS 50176             // 200704 bytes

__global__ __launch_bounds__(256) void fuse_kernel(
    const float* __restrict__ node_fea, const float* __restrict__ node_mask,
    const float* __restrict__ aw, const float* __restrict__ sw,
    float* __restrict__ out)
{
    extern __shared__ float sm2[];
    float* ssw   = sm2 + O_SSW;
    float* sawT  = sm2 + O_SAWT;
    float* su    = sm2 + O_SU;
    float* sth   = sm2 + O_STH;
    float* sgate = sm2 + O_SGATE;
    float* snbr_f= sm2 + O_SNBR;
    int*   snbr  = (int*)snbr_f;
    float* araw  = sm2 + O_ARAW;

    const int tid = threadIdx.x;
    const int b   = blockIdx.x >> 5;          // 32 blocks per batch
    const int n0  = (blockIdx.x & 31) * 64;

    // stage weights: sw [f][64] direct; aw [64 m][128 f] -> transpose via pad
    for (int idx = tid; idx < MM*128; idx += 256) {
        int m = idx >> 7, f = idx & 127;
        araw[m*129 + f] = aw[idx];
        ssw[idx] = sw[idx];
    }
    __syncthreads();
    for (int idx = tid; idx < MM*128; idx += 256) {
        int f = idx >> 6, m = idx & 63;
        sawT[idx] = araw[m*129 + f];
    }
    __syncthreads();   // araw dead after this; overlay regions reused below

    // stage edges: [c][k][n] layouts (pitch 66), theta -> [f=k*4+c][n] pitch 68
    for (int idx = tid; idx < 8192; idx += 256) {
        int c = idx >> 11, r = idx & 2047;    // r = n*32 + k
        size_t src = ((size_t)(b*CC + c)*NN + n0)*KK + r;
        int n = r >> 5, k = r & 31;
        sgate[c*2112 + k*66 + n] = g_gate[src];
        snbr [c*2112 + k*66 + n] = g_nbr[src];
        sth[(k*4 + c)*68 + n]    = g_theta[src];
    }
    __syncthreads();

    // phase A: su[f][n] = mask * gated feature (self f<16, neighbor f>=16 per c)
    {
        const int c = tid >> 6, nn = tid & 63;
        const float* nf = node_fea + (size_t)(b*CC + c) * NN * DD;
        const float mk = node_mask[b*NN + n0 + nn];
        const float G  = g_gsum[(size_t)(b*CC + c)*NN + n0 + nn];

        float4 a0 = {0,0,0,0}, a1 = {0,0,0,0}, a2 = {0,0,0,0}, a3 = {0,0,0,0};
        #pragma unroll 4
        for (int k = 0; k < KK; k++) {
            float g  = sgate[c*2112 + k*66 + nn];
            int   nb = snbr [c*2112 + k*66 + nn];
            const float4* vp = (const float4*)(nf + (size_t)nb * DD);
            float4 v0 = __ldg(vp), v1 = __ldg(vp+1), v2 = __ldg(vp+2), v3 = __ldg(vp+3);
            a0.x = fmaf(g, v0.x, a0.x); a0.y = fmaf(g, v0.y, a0.y);
            a0.z = fmaf(g, v0.z, a0.z); a0.w = fmaf(g, v0.w, a0.w);
            a1.x = fmaf(g, v1.x, a1.x); a1.y = fmaf(g, v1.y, a1.y);
            a1.z = fmaf(g, v1.z, a1.z); a1.w = fmaf(g, v1.w, a1.w);
            a2.x = fmaf(g, v2.x, a2.x); a2.y = fmaf(g, v2.y, a2.y);
            a2.z = fmaf(g, v2.z, a2.z); a2.w = fmaf(g, v2.w, a2.w);
            a3.x = fmaf(g, v3.x, a3.x); a3.y = fmaf(g, v3.y, a3.y);
            a3.z = fmaf(g, v3.z, a3.z); a3.w = fmaf(g, v3.w, a3.w);
        }
        const int fn = c*32 + 16;             // neighbor block
        su[(fn+ 0)*64+nn]=a0.x*mk; su[(fn+ 1)*64+nn]=a0.y*mk;
        su[(fn+ 2)*64+nn]=a0.z*mk; su[(fn+ 3)*64+nn]=a0.w*mk;
        su[(fn+ 4)*64+nn]=a1.x*mk; su[(fn+ 5)*64+nn]=a1.y*mk;
        su[(fn+ 6)*64+nn]=a1.z*mk; su[(fn+ 7)*64+nn]=a1.w*mk;
        su[(fn+ 8)*64+nn]=a2.x*mk; su[(fn+ 9)*64+nn]=a2.y*mk;
        su[(fn+10)*64+nn]=a2.z*mk; su[(fn+11)*64+nn]=a2.w*mk;
        su[(fn+12)*64+nn]=a3.x*mk; su[(fn+13)*64+nn]=a3.y*mk;
        su[(fn+14)*64+nn]=a3.z*mk; su[(fn+15)*64+nn]=a3.w*mk;

        const float Gm = G * mk;              // self block
        const float4* fp = (const float4*)(nf + (size_t)(n0+nn) * DD);
        const int fs = c*32;
        #pragma unroll
        for (int t4 = 0; t4 < 4; t4++) {
            float4 fv = __ldg(fp + t4);
            su[(fs+t4*4+0)*64+nn] = Gm*fv.x;  su[(fs+t4*4+1)*64+nn] = Gm*fv.y;
            su[(fs+t4*4+2)*64+nn] = Gm*fv.z;  su[(fs+t4*4+3)*64+nn] = Gm*fv.w;
        }
    }
    __syncthreads();

    // phase B: acc[4m][4n] = sum_f u'[f][n]*sw[f][m] + theta[f][n]*aw[m][f]
    {
        const int mg = (tid & 15) * 4;
        const int ng = (tid >> 4) * 4;
        float acc[4][4];
        #pragma unroll
        for (int a = 0; a < 4; a++)
            #pragma unroll
            for (int q = 0; q < 4; q++) acc[a][q] = 0.f;

        #pragma unroll 4
        for (int f = 0; f < 128; f++) {
            float4 w1 = *(const float4*)&ssw [f*64 + mg];
            float4 w2 = *(const float4*)&sawT[f*64 + mg];
            float4 uu = *(const float4*)&su  [f*64 + ng];
            float4 tt = *(const float4*)&sth [f*68 + ng];
            const float wm1[4] = {w1.x, w1.y, w1.z, w1.w};
            const float wm2[4] = {w2.x, w2.y, w2.z, w2.w};
            const float un[4]  = {uu.x, uu.y, uu.z, uu.w};
            const float tn[4]  = {tt.x, tt.y, tt.z, tt.w};
            #pragma unroll
            for (int a = 0; a < 4; a++)
                #pragma unroll
                for (int q = 0; q < 4; q++)
                    acc[a][q] = fmaf(wm1[a], un[q], fmaf(wm2[a], tn[q], acc[a][q]));
        }

        float mkq[4];
        #pragma unroll
        for (int q = 0; q < 4; q++) mkq[q] = node_mask[b*NN + n0 + ng + q];

        #pragma unroll
        for (int a = 0; a < 4; a++) {
            float4 o4;
            float v0 = acc[a][0], v1 = acc[a][1], v2 = acc[a][2], v3 = acc[a][3];
            v0 = (v0 >= 0.f) ? v0 : 0.01f*v0;  v1 = (v1 >= 0.f) ? v1 : 0.01f*v1;
            v2 = (v2 >= 0.f) ? v2 : 0.01f*v2;  v3 = (v3 >= 0.f) ? v3 : 0.01f*v3;
            o4.x = v0*mkq[0]; o4.y = v1*mkq[1]; o4.z = v2*mkq[2]; o4.w = v3*mkq[3];
            *(float4*)&out[((size_t)b*MM + mg + a)*NN + n0 + ng] = o4;
        }
    }
}

// ---------------------------------------------------------------------------
extern "C" void kernel_launch(void* const* d_in, const int* in_sizes, int n_in,
                              void* d_out, int out_size)
{
    const float* pos       = (const float*)d_in[0];
    const float* node_fea  = (const float*)d_in[1];
    const float* node_mask = (const float*)d_in[2];
    const float* aw        = (const float*)d_in[3];
    const float* sw        = (const float*)d_in[4];
    const float* rw1       = (const float*)d_in[5];
    const float* rw2       = (const float*)d_in[6];
    float* out = (float*)d_out;

    const int smem1 = 65536;
    const int smem2 = SMEM2_FLOATS * 4;
    cudaFuncSetAttribute(knn_kernel,  cudaFuncAttributeMaxDynamicSharedMemorySize, smem1);
    cudaFuncSetAttribute(fuse_kernel, cudaFuncAttributeMaxDynamicSharedMemorySize, smem2);

    knn_kernel<<<dim3(NN/ROWS1, BSZ*CC), 512, smem1>>>(pos, node_mask, rw1, rw2);
    fuse_kernel<<<BSZ*(NN/64), 256, smem2>>>(node_fea, node_mask, aw, sw, out);
}